// round 13
// baseline (speedup 1.0000x reference)
#include <cuda_runtime.h>

#define BB   1024
#define CC   3
#define PROW 4
#define PCOL 5
#define PP   20      // PROW*PCOL
#define HID  32
#define HH   224
#define WW   220
#define PH   56      // HH/PROW
#define PW   44      // WW/PCOL
#define W4   55      // WW/4 float4 per row
#define PW4  11      // PW/4 float4 per column-patch

#define KG   4                    // k-groups per (image,patch)
#define KS   (HID / KG)           // 8 k's per group
#define IPB  4                    // images per MLP block
#define MLPT (IPB * PP * KG)      // 320 threads
#define NMLPB (BB / IPB)          // 256 blocks

// per-(image, patch, channel) partial sums
__device__ float g_scratch[BB * PP * CC];

// ---------------------------------------------------------------------------
// Kernel 1: pooling — unchanged data path (measured 6.83 TB/s, HBM wall).
// grid = (BB, CC); block = (56, 8). Late PDL trigger at block end so the
// dependent MLP kernel can launch during the drain without displacing
// resident pool blocks mid-stream.
// ---------------------------------------------------------------------------
__global__ __launch_bounds__(448)
void nam_pool_kernel(const float* __restrict__ x)
{
    const int b  = blockIdx.x;
    const int c  = blockIdx.y;
    const int tx = threadIdx.x;   // 0..55 (55 idle for loads)
    const int ty = threadIdx.y;   // 0..7

    const float4* base = (const float4*)(x) + (size_t)(b * CC + c) * (HH * W4);

    float acc[PROW] = {0.f, 0.f, 0.f, 0.f};

    if (tx < W4) {
        #pragma unroll
        for (int pr = 0; pr < PROW; pr++) {
            #pragma unroll
            for (int i = 0; i < PH / 8; i++) {          // 7 row-groups
                const int h = pr * PH + i * 8 + ty;
                float4 v = base[h * W4 + tx];
                acc[pr] += (v.x + v.y) + (v.z + v.w);
            }
        }
    }

    __shared__ float part[PROW][8][56];
    #pragma unroll
    for (int pr = 0; pr < PROW; pr++)
        part[pr][ty][tx] = acc[pr];                      // tx==55 stores 0
    __syncthreads();

    const int tid = ty * 56 + tx;
    if (tid < PP) {
        const int pr = tid / PCOL;
        const int pc = tid % PCOL;
        float s = 0.f;
        #pragma unroll
        for (int yy = 0; yy < 8; yy++) {
            float a = 0.f;
            #pragma unroll
            for (int k = 0; k < PW4; k++)
                a += part[pr][yy][pc * PW4 + k];
            s += a;
        }
        g_scratch[(b * PP + tid) * CC + c] = s;
    }

    // Late trigger: fires once all blocks reach here -> dependent grid
    // launches during our drain instead of after host-side completion.
    cudaTriggerProgrammaticLaunchCompletion();
}

// ---------------------------------------------------------------------------
// Kernel 2: MLP (k-parallel, staging-free). PDL: prefetch all weights
// BEFORE cudaGridDependencySynchronize() (independent of kernel 1), so the
// only post-dependency work is 3 scratch loads + 16 FMAs + 2 shfls.
// grid = 256, block = 320. Thread t = ((i*PP + p)*KG + kg).
// ---------------------------------------------------------------------------
__global__ __launch_bounds__(MLPT)
void nam_mlp_kernel(const float* __restrict__ w1,
                    const float* __restrict__ b1,
                    const float* __restrict__ w2,
                    const float* __restrict__ b2,
                    float* __restrict__ out)
{
    __shared__ float scon[IPB][PP];

    const int t  = threadIdx.x;
    const int kg = t & (KG - 1);          // 0..3
    const int ip = t >> 2;                // (i*PP + p), 0..79
    const int p  = ip % PP;
    const int i  = ip / PP;
    const int b  = blockIdx.x * IPB + i;

    // ---- prefetch phase (no dependency on kernel 1) ----
    const int base = p * HID + kg * KS;
    const float4* w1v = (const float4*)(w1 + base);
    const float4* b1v = (const float4*)(b1 + base);
    const float4* w2v = (const float4*)(w2 + base);

    float4 a0 = w1v[0], a1 = w1v[1];
    float4 c0 = b1v[0], c1 = b1v[1];
    float4 g0 = w2v[0], g1 = w2v[1];
    const float bias2 = (kg == 0) ? b2[p] : 0.f;

    // ---- wait for pool kernel's memory to be visible ----
    cudaGridDependencySynchronize();

    const float* sp = &g_scratch[(b * PP + p) * CC];
    const float f = (sp[0] + sp[1] + sp[2]) * (1.0f / (CC * PH * PW));

    float o = 0.f;
    o = fmaf(fmaxf(fmaf(f, a0.x, c0.x), 0.f), g0.x, o);
    o = fmaf(fmaxf(fmaf(f, a0.y, c0.y), 0.f), g0.y, o);
    o = fmaf(fmaxf(fmaf(f, a0.z, c0.z), 0.f), g0.z, o);
    o = fmaf(fmaxf(fmaf(f, a0.w, c0.w), 0.f), g0.w, o);
    o = fmaf(fmaxf(fmaf(f, a1.x, c1.x), 0.f), g1.x, o);
    o = fmaf(fmaxf(fmaf(f, a1.y, c1.y), 0.f), g1.y, o);
    o = fmaf(fmaxf(fmaf(f, a1.z, c1.z), 0.f), g1.z, o);
    o = fmaf(fmaxf(fmaf(f, a1.w, c1.w), 0.f), g1.w, o);

    // reduce the 4 kg-lanes (aligned 4-lane groups within a warp)
    o += __shfl_down_sync(0xFFFFFFFFu, o, 2);
    o += __shfl_down_sync(0xFFFFFFFFu, o, 1);

    if (kg == 0) {
        o += bias2;
        out[BB + b * PP + p] = o;         // contribs section
        scon[i][p] = o;
    }
    __syncthreads();

    if (t < IPB) {
        float sc = 0.f;
        #pragma unroll
        for (int q = 0; q < PP; q++)
            sc += scon[t][q];
        out[blockIdx.x * IPB + t] = sc;   // score section
    }
}

extern "C" void kernel_launch(void* const* d_in, const int* in_sizes, int n_in,
                              void* d_out, int out_size)
{
    const float* x  = (const float*)d_in[0];
    const float* w1 = (const float*)d_in[1];
    const float* b1 = (const float*)d_in[2];
    const float* w2 = (const float*)d_in[3];
    const float* b2 = (const float*)d_in[4];
    float* out = (float*)d_out;

    nam_pool_kernel<<<dim3(BB, CC), dim3(56, 8)>>>(x);

    cudaLaunchConfig_t cfg = {};
    cfg.gridDim  = dim3(NMLPB, 1, 1);
    cfg.blockDim = dim3(MLPT, 1, 1);
    cfg.dynamicSmemBytes = 0;
    cfg.stream = 0;
    cudaLaunchAttribute attr[1];
    attr[0].id = cudaLaunchAttributeProgrammaticStreamSerialization;
    attr[0].val.programmaticStreamSerializationAllowed = 1;
    cfg.attrs = attr;
    cfg.numAttrs = 1;
    cudaLaunchKernelEx(&cfg, nam_mlp_kernel, w1, b1, w2, b2, out);
}

// round 16
// speedup vs baseline: 1.0166x; 1.0166x over previous
#include <cuda_runtime.h>

#define BB   1024
#define CC   3
#define PROW 4
#define PCOL 5
#define PP   20      // PROW*PCOL
#define HID  32
#define HH   224
#define WW   220
#define PH   56      // HH/PROW
#define PW   44      // WW/PCOL
#define W4   55      // WW/4 float4 per row
#define PW4  11      // PW/4 float4 per column-patch

#define KG   8                    // k-lanes per (image,patch)
#define KS   (HID / KG)           // 4 k's per lane (one float4)
#define IPB  2                    // images per MLP block
#define MLPT (IPB * PP * KG)      // 320 threads
#define NMLPB (BB / IPB)          // 512 blocks

// per-(image, patch, channel) partial sums
__device__ float g_scratch[BB * PP * CC];

// ---------------------------------------------------------------------------
// Kernel 1: pooling — proven config (grid (BB,CC), block (56,8), regs 32,
// occ ~83%) + __ldcs: x is streamed exactly once (605MB >> L2), so
// evict-first keeps L2 insertion churn off the critical path.
// ---------------------------------------------------------------------------
__global__ __launch_bounds__(448)
void nam_pool_kernel(const float* __restrict__ x)
{
    const int b  = blockIdx.x;
    const int c  = blockIdx.y;
    const int tx = threadIdx.x;   // 0..55 (55 idle for loads)
    const int ty = threadIdx.y;   // 0..7

    const float4* base = (const float4*)(x) + (size_t)(b * CC + c) * (HH * W4);

    float acc[PROW] = {0.f, 0.f, 0.f, 0.f};

    if (tx < W4) {
        #pragma unroll
        for (int pr = 0; pr < PROW; pr++) {
            #pragma unroll
            for (int i = 0; i < PH / 8; i++) {          // 7 row-groups
                const int h = pr * PH + i * 8 + ty;
                float4 v = __ldcs(&base[h * W4 + tx]);
                acc[pr] += (v.x + v.y) + (v.z + v.w);
            }
        }
    }

    __shared__ float part[PROW][8][56];
    #pragma unroll
    for (int pr = 0; pr < PROW; pr++)
        part[pr][ty][tx] = acc[pr];                      // tx==55 stores 0
    __syncthreads();

    const int tid = ty * 56 + tx;
    if (tid < PP) {
        const int pr = tid / PCOL;
        const int pc = tid % PCOL;
        float s = 0.f;
        #pragma unroll
        for (int yy = 0; yy < 8; yy++) {
            float a = 0.f;
            #pragma unroll
            for (int k = 0; k < PW4; k++)
                a += part[pr][yy][pc * PW4 + k];
            s += a;
        }
        g_scratch[(b * PP + tid) * CC + c] = s;
    }
}

// ---------------------------------------------------------------------------
// Kernel 2: MLP, KG=8 lanes per (image,patch): each lane = one float4 of
// w1/b1/w2 (consecutive lanes -> consecutive 16B, fully coalesced), chain =
// 4 accum FMAs + 3 shfl steps. grid = 512, block = 320.
// ---------------------------------------------------------------------------
__global__ __launch_bounds__(MLPT)
void nam_mlp_kernel(const float* __restrict__ w1,
                    const float* __restrict__ b1,
                    const float* __restrict__ w2,
                    const float* __restrict__ b2,
                    float* __restrict__ out)
{
    __shared__ float scon[IPB][PP];

    const int t  = threadIdx.x;
    const int kg = t & (KG - 1);          // 0..7
    const int ip = t >> 3;                // (i*PP + p), 0..39
    const int p  = ip % PP;
    const int i  = ip / PP;
    const int b  = blockIdx.x * IPB + i;

    // feature for (b, p): all 8 kg-lanes read the same 3 floats (1 line)
    const float* sp = &g_scratch[(b * PP + p) * CC];
    const float f = (sp[0] + sp[1] + sp[2]) * (1.0f / (CC * PH * PW));

    // this lane's float4 slice of each weight array (coalesced)
    const int base = p * HID + kg * KS;
    const float4 a0 = *(const float4*)(w1 + base);
    const float4 c0 = *(const float4*)(b1 + base);
    const float4 g0 = *(const float4*)(w2 + base);

    float o = 0.f;
    o = fmaf(fmaxf(fmaf(f, a0.x, c0.x), 0.f), g0.x, o);
    o = fmaf(fmaxf(fmaf(f, a0.y, c0.y), 0.f), g0.y, o);
    o = fmaf(fmaxf(fmaf(f, a0.z, c0.z), 0.f), g0.z, o);
    o = fmaf(fmaxf(fmaf(f, a0.w, c0.w), 0.f), g0.w, o);

    // reduce the 8 kg-lanes (aligned 8-lane groups within a warp)
    o += __shfl_down_sync(0xFFFFFFFFu, o, 4);
    o += __shfl_down_sync(0xFFFFFFFFu, o, 2);
    o += __shfl_down_sync(0xFFFFFFFFu, o, 1);

    if (kg == 0) {
        o += b2[p];
        out[BB + b * PP + p] = o;         // contribs section
        scon[i][p] = o;
    }
    __syncthreads();

    if (t < IPB) {
        float sc = 0.f;
        #pragma unroll
        for (int q = 0; q < PP; q++)
            sc += scon[t][q];
        out[blockIdx.x * IPB + t] = sc;   // score section
    }
}

extern "C" void kernel_launch(void* const* d_in, const int* in_sizes, int n_in,
                              void* d_out, int out_size)
{
    const float* x  = (const float*)d_in[0];
    const float* w1 = (const float*)d_in[1];
    const float* b1 = (const float*)d_in[2];
    const float* w2 = (const float*)d_in[3];
    const float* b2 = (const float*)d_in[4];
    float* out = (float*)d_out;

    nam_pool_kernel<<<dim3(BB, CC), dim3(56, 8)>>>(x);
    nam_mlp_kernel<<<NMLPB, MLPT>>>(w1, b1, w2, b2, out);
}